// round 10
// baseline (speedup 1.0000x reference)
#include <cuda_runtime.h>
#include <cstdint>

// Problem constants
#define D_MODEL   1024
#define N_HEADS   16
#define HEAD_DIM  64
#define BATCH     2
#define TQ        2048
#define TCACHE    2048
#define TKTOT     4096
#define MROWS     4096

#define OUT_ELEMS (MROWS * D_MODEL)
#define KV_ELEMS  (BATCH * N_HEADS * TKTOT * HEAD_DIM)

// Scratch (device globals — no allocation allowed)
__device__ float g_q[BATCH * N_HEADS * TQ * HEAD_DIM];    // [b,h,t,d]
__device__ float g_att[MROWS * D_MODEL];                  // [b,t,h,d] row-major [4096,1024]

// ---------------------------------------------------------------------------
// helpers
// ---------------------------------------------------------------------------
__device__ __forceinline__ unsigned f2tf(float x) {
    unsigned u;
    asm("cvt.rna.tf32.f32 %0, %1;" : "=r"(u) : "f"(x));
    return u;
}

__device__ __forceinline__ void mma8(float* c, const unsigned* a, unsigned b0, unsigned b1) {
    asm volatile(
        "mma.sync.aligned.m16n8k8.row.col.f32.tf32.tf32.f32 "
        "{%0,%1,%2,%3}, {%4,%5,%6,%7}, {%8,%9}, {%0,%1,%2,%3};\n"
        : "+f"(c[0]), "+f"(c[1]), "+f"(c[2]), "+f"(c[3])
        : "r"(a[0]), "r"(a[1]), "r"(a[2]), "r"(a[3]), "r"(b0), "r"(b1));
}

// Fragment-packed layouts (tf32 as u32):
//  A-frag block (16 rows x 8 k): pitch APITCH u32; element (r,k):
//    lane=(r&7)*4+(k&3), reg=((r>>3)&1)+2*((k>>2)&1); u32 off = lane*4+reg.
//    Consumer: uint4 at blk*APITCH + lane*4  (LDS.128, conflict-free).
//  B-frag block (8 k x 8 n): pitch BPITCH u32; element (k,n):
//    lane=(n&7)*4+(k&3), comp=(k>>2)&1; u32 off = lane*2+comp.
//    Consumer: uint2 at blk*BPITCH + lane*2  (LDS.64, conflict-free).
#define APITCH 132
#define BPITCH 66

// ---------------------------------------------------------------------------
// 1) Cache copy (k/v rows [0, TCACHE))
// ---------------------------------------------------------------------------
__global__ void copy_cache_kernel(const float4* __restrict__ kc,
                                  const float4* __restrict__ vc,
                                  float4* __restrict__ kout,
                                  float4* __restrict__ vout) {
    int idx = blockIdx.x * blockDim.x + threadIdx.x;  // 0 .. 1048575
    int chunk = idx >> 15;
    int off   = idx & 32767;
    int dst   = (chunk << 16) + off;
    kout[dst] = kc[idx];
    vout[dst] = vc[idx];
}

// ---------------------------------------------------------------------------
// 2) TF32 GEMM: Y[4096,1024] = X[4096,1024] @ W[1024,1024] + bias
//    CTA 128x128, BK=16, 8 warps (64x32 warp tiles), fragment-packed smem.
//    Ap: 8 rowtiles x 2 ks blocks  (16 * APITCH u32)
//    Bp: 16 ntiles  x 2 ks blocks  (32 * BPITCH u32)
// ---------------------------------------------------------------------------
template<int MODE>
__device__ __forceinline__ void gemm_core(const float* __restrict__ X,
                                          const float* __restrict__ W,
                                          const float* __restrict__ bias,
                                          float* __restrict__ dst,
                                          unsigned* Ap, unsigned* Bp) {
    const int tid = threadIdx.x;
    const int lane = tid & 31, w = tid >> 5;
    const int gi = lane >> 2, ti = lane & 3;
    const int wm = w & 1, wn = w >> 1;
    const int row0 = blockIdx.y * 128, col0 = blockIdx.x * 128;

    float acc[4][4][4] = {};

    const int xr = tid >> 1, xk = (tid & 1) * 8;
    const int wk = tid >> 4, wn0 = (tid & 15) * 8;
    const float* Xp = X + (size_t)(row0 + xr) * D_MODEL + xk;
    const float* Wp = W + (size_t)wk * D_MODEL + col0 + wn0;

    // A store bases (thread writes rows xr, k = xk..xk+7)
    const int ablk = (xr >> 4) * 2 + (xk >> 3);
    const int abase = ablk * APITCH + (xr & 7) * 16 + ((xr >> 3) & 1);
    // B store bases (thread writes k = wk, n = wn0..wn0+7)
    const int bcomp = (wk >> 2) & 1;
    const int bblk0 = (wn0 >> 3) * 2 + (wk >> 3);
    const int bbase = bblk0 * BPITCH + (wk & 3) * 2 + bcomp;

    float4 xa = *(const float4*)Xp;
    float4 xb = *(const float4*)(Xp + 4);
    float4 wa = *(const float4*)Wp;
    float4 wb = *(const float4*)(Wp + 4);

    for (int k0 = 0; k0 < D_MODEL; k0 += 16) {
        // pack A fragments
        Ap[abase + 0]  = f2tf(xa.x);
        Ap[abase + 4]  = f2tf(xa.y);
        Ap[abase + 8]  = f2tf(xa.z);
        Ap[abase + 12] = f2tf(xa.w);
        Ap[abase + 2]  = f2tf(xb.x);
        Ap[abase + 6]  = f2tf(xb.y);
        Ap[abase + 10] = f2tf(xb.z);
        Ap[abase + 14] = f2tf(xb.w);
        // pack B fragments (lane = (n&7)*4 + (wk&3) -> +8 u32 per n step)
        Bp[bbase + 0]  = f2tf(wa.x);
        Bp[bbase + 8]  = f2tf(wa.y);
        Bp[bbase + 16] = f2tf(wa.z);
        Bp[bbase + 24] = f2tf(wa.w);
        Bp[bbase + 32] = f2tf(wb.x);
        Bp[bbase + 40] = f2tf(wb.y);
        Bp[bbase + 48] = f2tf(wb.z);
        Bp[bbase + 56] = f2tf(wb.w);
        __syncthreads();
        if (k0 + 16 < D_MODEL) {
            xa = *(const float4*)(Xp + k0 + 16);
            xb = *(const float4*)(Xp + k0 + 20);
            wa = *(const float4*)(Wp + (size_t)(k0 + 16) * D_MODEL);
            wb = *(const float4*)(Wp + (size_t)(k0 + 16) * D_MODEL + 4);
        }
#pragma unroll
        for (int ks = 0; ks < 2; ks++) {
            uint4 af[4];
#pragma unroll
            for (int mt = 0; mt < 4; mt++)
                af[mt] = *(const uint4*)&Ap[(((wm * 4 + mt) * 2 + ks)) * APITCH + lane * 4];
#pragma unroll
            for (int nt = 0; nt < 4; nt++) {
                uint2 bf = *(const uint2*)&Bp[(((wn * 4 + nt) * 2 + ks)) * BPITCH + lane * 2];
#pragma unroll
                for (int mt = 0; mt < 4; mt++)
                    mma8(acc[mt][nt], (const unsigned*)&af[mt], bf.x, bf.y);
            }
        }
        __syncthreads();
    }

    // Epilogue: bias + scatter (float2 granularity)
#pragma unroll
    for (int mt = 0; mt < 4; mt++) {
#pragma unroll
        for (int nt = 0; nt < 4; nt++) {
            int row = row0 + wm * 64 + mt * 16 + gi;
            int col = col0 + wn * 32 + nt * 8 + 2 * ti;
            float2 bb = *(const float2*)&bias[col];
            float2 v0 = make_float2(acc[mt][nt][0] + bb.x, acc[mt][nt][1] + bb.y);
            float2 v1 = make_float2(acc[mt][nt][2] + bb.x, acc[mt][nt][3] + bb.y);
#pragma unroll
            for (int p = 0; p < 2; p++) {
                int r = row + p * 8;
                float2 v = p ? v1 : v0;
                size_t idx;
                if (MODE == 2) {
                    idx = (size_t)r * D_MODEL + col;
                } else {
                    int b = r >> 11, t = r & 2047;
                    int h = col >> 6, d = col & 63;
                    if (MODE == 0)
                        idx = ((size_t)(b * N_HEADS + h) * TQ + t) * HEAD_DIM + d;
                    else
                        idx = ((size_t)(b * N_HEADS + h) * TKTOT + TCACHE + t) * HEAD_DIM + d;
                }
                *(float2*)&dst[idx] = v;
            }
        }
    }
}

__global__ void __launch_bounds__(256, 2) qkv_kernel(
        const float* __restrict__ x,
        const float* __restrict__ Wq, const float* __restrict__ bq,
        const float* __restrict__ Wk, const float* __restrict__ bk,
        const float* __restrict__ Wv, const float* __restrict__ bv,
        float* __restrict__ kout, float* __restrict__ vout) {
    __shared__ unsigned Ap[16 * APITCH];
    __shared__ unsigned Bp[32 * BPITCH];
    int z = blockIdx.z;
    if (z == 0)      gemm_core<0>(x, Wq, bq, g_q,  Ap, Bp);
    else if (z == 1) gemm_core<1>(x, Wk, bk, kout, Ap, Bp);
    else             gemm_core<1>(x, Wv, bv, vout, Ap, Bp);
}

__global__ void __launch_bounds__(256, 2) oproj_kernel(
        const float* __restrict__ Wo, const float* __restrict__ bo,
        float* __restrict__ out) {
    __shared__ unsigned Ap[16 * APITCH];
    __shared__ unsigned Bp[32 * BPITCH];
    gemm_core<2>(g_att, Wo, bo, out, Ap, Bp);
}

// ---------------------------------------------------------------------------
// 3) Flash attention, tensor-core TF32 with fragment-packed Q/K/V.
//    CTA: 128 q-rows x (b,h); 128 threads = 4 warps x 32 q-rows; K-tile 64.
//    Qp: 8 rowtiles x 8 ks  (64 * APITCH u32)  -- packed ONCE
//    Ps (unpacked rows, pitch 68): written per tile from C-frags
//    Kp: 8 ntiles x 8 ks    (64 * BPITCH u32)
//    Vp: 8 ntiles x 8 ks    (64 * BPITCH u32)
// ---------------------------------------------------------------------------
#define QP_U32 (64 * APITCH)        // 8448
#define PS_U32 (128 * 68)           // 8704
#define KP_U32 (64 * BPITCH)        // 4224
#define VP_U32 (64 * BPITCH)        // 4224
#define AT_SMEM_BYTES ((QP_U32 + PS_U32 + KP_U32 + VP_U32) * 4)

__global__ void __launch_bounds__(128, 2) attn_kernel(const float* __restrict__ Kg,
                                                      const float* __restrict__ Vg) {
    extern __shared__ unsigned smu[];
    unsigned* Qp = smu;
    unsigned* Ps = Qp + QP_U32;
    unsigned* Kp = Ps + PS_U32;
    unsigned* Vp = Kp + KP_U32;

    const int tid = threadIdx.x;
    const int lane = tid & 31, w = tid >> 5;
    const int gi = lane >> 2, ti = lane & 3;
    const int qt = (int)gridDim.x - 1 - (int)blockIdx.x;   // big tiles first
    const int bh = blockIdx.y;
    const int i0 = qt << 7;
    const int rbw = w * 32;

    const float* Qg = g_q + (size_t)bh * (TQ * HEAD_DIM);
    const float* Kb = Kg + (size_t)bh * (TKTOT * HEAD_DIM);
    const float* Vb = Vg + (size_t)bh * (TKTOT * HEAD_DIM);

    // ---- Load + pack Q tile once (pre-scaled by 0.125) ----
#pragma unroll
    for (int it = 0; it < 16; it++) {
        int fid = it * 128 + tid;          // float4 idx 0..2047
        int r = fid >> 4, d0 = (fid & 15) << 2;
        float4 q = *(const float4*)&Qg[(size_t)(i0 + r) * 64 + d0];
        int blk = (r >> 4) * 8 + (d0 >> 3);
        int base = blk * APITCH + (r & 7) * 16 + ((r >> 3) & 1) + 2 * ((d0 >> 2) & 1);
        Qp[base + 0]  = f2tf(q.x * 0.125f);
        Qp[base + 4]  = f2tf(q.y * 0.125f);
        Qp[base + 8]  = f2tf(q.z * 0.125f);
        Qp[base + 12] = f2tf(q.w * 0.125f);
    }

    float O[2][8][4] = {};
    float mrow[2][2], lrow[2][2];
#pragma unroll
    for (int mt = 0; mt < 2; mt++)
        for (int p = 0; p < 2; p++) { mrow[mt][p] = -1e30f; lrow[mt][p] = 0.0f; }

    const int ntiles = 2 * qt + 34;
    const int mstart = 2 * qt + 32;

    for (int kt = 0; kt < ntiles; kt++) {
        const int j0 = kt << 6;
        __syncthreads();                   // prev-iter readers of Kp/Vp done
        // ---- Load + pack K (B-frag for S) and V (B-frag for PV) ----
#pragma unroll
        for (int it = 0; it < 8; it++) {
            int fid = it * 128 + tid;      // float4 idx 0..1023
            int j = fid >> 4, d0 = (fid & 15) << 2;
            float4 kv = *(const float4*)&Kb[(size_t)(j0 + j) * 64 + d0];
            // K element (k=d, n=j)
            int kblk = (j >> 3) * 8 + (d0 >> 3);
            int kbase = kblk * BPITCH + (j & 7) * 8 + ((d0 >> 2) & 1);
            Kp[kbase + 0] = f2tf(kv.x);
            Kp[kbase + 2] = f2tf(kv.y);
            Kp[kbase + 4] = f2tf(kv.z);
            Kp[kbase + 6] = f2tf(kv.w);
            float4 vv = *(const float4*)&Vb[(size_t)(j0 + j) * 64 + d0];
            // V element (k=j, n=d)
            int vblk = (d0 >> 3) * 8 + (j >> 3);
            int vbase = vblk * BPITCH + (d0 & 7) * 8 + (j & 3) * 2 + ((j >> 2) & 1);
            Vp[vbase + 0]  = f2tf(vv.x);
            Vp[vbase + 8]  = f2tf(vv.y);
            Vp[vbase + 16] = f2tf(vv.z);
            Vp[vbase + 24] = f2tf(vv.w);
        }
        __syncthreads();

        // ---- S = Q K^T ----
        float S[2][8][4] = {};
#pragma unroll
        for (int ks = 0; ks < 8; ks++) {
            uint4 af[2];
            af[0] = *(const uint4*)&Qp[(((w * 2 + 0) * 8 + ks)) * APITCH + lane * 4];
            af[1] = *(const uint4*)&Qp[(((w * 2 + 1) * 8 + ks)) * APITCH + lane * 4];
#pragma unroll
            for (int nt = 0; nt < 8; nt++) {
                uint2 bf = *(const uint2*)&Kp[((nt * 8 + ks)) * BPITCH + lane * 2];
                mma8(S[0][nt], (const unsigned*)&af[0], bf.x, bf.y);
                mma8(S[1][nt], (const unsigned*)&af[1], bf.x, bf.y);
            }
        }

        // ---- causal mask (last two tiles only) ----
        if (kt >= mstart) {
#pragma unroll
            for (int mt = 0; mt < 2; mt++)
#pragma unroll
                for (int p = 0; p < 2; p++) {
                    int i = i0 + rbw + mt * 16 + gi + p * 8;
#pragma unroll
                    for (int nt = 0; nt < 8; nt++) {
                        int j = j0 + nt * 8 + 2 * ti;
                        if (j     > i + TCACHE) S[mt][nt][2 * p]     = -1e30f;
                        if (j + 1 > i + TCACHE) S[mt][nt][2 * p + 1] = -1e30f;
                    }
                }
        }

        // ---- online softmax (quad reductions) ----
        float alpha[2][2];
#pragma unroll
        for (int mt = 0; mt < 2; mt++)
#pragma unroll
            for (int p = 0; p < 2; p++) {
                float mx = -1e30f;
#pragma unroll
                for (int nt = 0; nt < 8; nt++)
                    mx = fmaxf(mx, fmaxf(S[mt][nt][2 * p], S[mt][nt][2 * p + 1]));
                mx = fmaxf(mx, __shfl_xor_sync(0xffffffffu, mx, 1));
                mx = fmaxf(mx, __shfl_xor_sync(0xffffffffu, mx, 2));
                float mn = fmaxf(mrow[mt][p], mx);
                alpha[mt][p] = __expf(mrow[mt][p] - mn);
                mrow[mt][p] = mn;
                float ls = 0.0f;
#pragma unroll
                for (int nt = 0; nt < 8; nt++) {
                    float e0 = __expf(S[mt][nt][2 * p]     - mn);
                    float e1 = __expf(S[mt][nt][2 * p + 1] - mn);
                    S[mt][nt][2 * p] = e0;
                    S[mt][nt][2 * p + 1] = e1;
                    ls += e0 + e1;
                }
                ls += __shfl_xor_sync(0xffffffffu, ls, 1);
                ls += __shfl_xor_sync(0xffffffffu, ls, 2);
                lrow[mt][p] = lrow[mt][p] * alpha[mt][p] + ls;
            }

        // ---- write P to smem (row layout), rescale O ----
#pragma unroll
        for (int mt = 0; mt < 2; mt++) {
            int r1 = rbw + mt * 16 + gi;
#pragma unroll
            for (int nt = 0; nt < 8; nt++) {
                *(uint2*)&Ps[r1 * 68 + nt * 8 + 2 * ti] =
                    make_uint2(f2tf(S[mt][nt][0]), f2tf(S[mt][nt][1]));
                *(uint2*)&Ps[(r1 + 8) * 68 + nt * 8 + 2 * ti] =
                    make_uint2(f2tf(S[mt][nt][2]), f2tf(S[mt][nt][3]));
                O[mt][nt][0] *= alpha[mt][0];
                O[mt][nt][1] *= alpha[mt][0];
                O[mt][nt][2] *= alpha[mt][1];
                O[mt][nt][3] *= alpha[mt][1];
            }
        }
        __syncwarp();                      // Ps rows produced+consumed within warp

        // ---- O += P V ----
#pragma unroll
        for (int ks = 0; ks < 8; ks++) {
            unsigned af[2][4];
#pragma unroll
            for (int mt = 0; mt < 2; mt++) {
                int rb = rbw + mt * 16;
                af[mt][0] = Ps[(rb + gi)     * 68 + ks * 8 + ti];
                af[mt][1] = Ps[(rb + gi + 8) * 68 + ks * 8 + ti];
                af[mt][2] = Ps[(rb + gi)     * 68 + ks * 8 + ti + 4];
                af[mt][3] = Ps[(rb + gi + 8) * 68 + ks * 8 + ti + 4];
            }
#pragma unroll
            for (int nt = 0; nt < 8; nt++) {
                uint2 bf = *(const uint2*)&Vp[((nt * 8 + ks)) * BPITCH + lane * 2];
                mma8(O[0][nt], af[0], bf.x, bf.y);
                mma8(O[1][nt], af[1], bf.x, bf.y);
            }
        }
    }

    // ---- epilogue: normalize + write g_att [b,t,h,d] ----
    const int b = bh >> 4, h = bh & 15;
#pragma unroll
    for (int mt = 0; mt < 2; mt++) {
        float inv0 = 1.0f / lrow[mt][0];
        float inv1 = 1.0f / lrow[mt][1];
        int r1 = i0 + rbw + mt * 16 + gi;
#pragma unroll
        for (int nt = 0; nt < 8; nt++) {
            int d = nt * 8 + 2 * ti;
            *(float2*)&g_att[((size_t)(b * TQ + r1) * N_HEADS + h) * HEAD_DIM + d] =
                make_float2(O[mt][nt][0] * inv0, O[mt][nt][1] * inv0);
            *(float2*)&g_att[((size_t)(b * TQ + r1 + 8) * N_HEADS + h) * HEAD_DIM + d] =
                make_float2(O[mt][nt][2] * inv1, O[mt][nt][3] * inv1);
        }
    }
}

// ---------------------------------------------------------------------------
extern "C" void kernel_launch(void* const* d_in, const int* in_sizes, int n_in,
                              void* d_out, int out_size) {
    (void)in_sizes; (void)n_in; (void)out_size;
    const float* x  = (const float*)d_in[0];
    const float* kc = (const float*)d_in[1];
    const float* vc = (const float*)d_in[2];
    const float* Wq = (const float*)d_in[3];
    const float* bq = (const float*)d_in[4];
    const float* Wk = (const float*)d_in[5];
    const float* bk = (const float*)d_in[6];
    const float* Wv = (const float*)d_in[7];
    const float* bv = (const float*)d_in[8];
    const float* Wo = (const float*)d_in[9];
    const float* bo = (const float*)d_in[10];

    float* out   = (float*)d_out;
    float* k_out = out + OUT_ELEMS;
    float* v_out = k_out + KV_ELEMS;

    copy_cache_kernel<<<4096, 256>>>((const float4*)kc, (const float4*)vc,
                                     (float4*)k_out, (float4*)v_out);

    qkv_kernel<<<dim3(8, 32, 3), 256>>>(x, Wq, bq, Wk, bk, Wv, bv, k_out, v_out);

    cudaFuncSetAttribute(attn_kernel, cudaFuncAttributeMaxDynamicSharedMemorySize,
                         AT_SMEM_BYTES);
    attn_kernel<<<dim3(TQ / 128, BATCH * N_HEADS), 128, AT_SMEM_BYTES>>>(k_out, v_out);

    oproj_kernel<<<dim3(8, 32), 256>>>(Wo, bo, out);
}